// round 16
// baseline (speedup 1.0000x reference)
#include <cuda_runtime.h>
#include <cuda_fp16.h>
#include <cstdint>
#include <cstddef>

// ---------------- problem constants ----------------
static constexpr int Bm = 1024;     // batch rows
static constexpr int Dk = 512;      // feature dim (K)
static constexpr int Cn = 100000;   // classes (N)
static constexpr float S_s = 30.0f;
static constexpr float M_m = 0.4f;

// GEMM config
#define BMT 128
#define BNT 128
#define BKT 32
static constexpr int NCHUNK = Dk / BKT;   // 16
static constexpr int A_STAGES = 4;
static constexpr int A_STAGE = BMT * BKT * 2;   // 8192 B
static constexpr int B_STAGE = BKT * BNT * 2;   // 8192 B (fp16, double buffered)
static constexpr int OFF_B = A_STAGES * A_STAGE;            // 32768
static constexpr int SMEM_BYTES = OFF_B + 2 * B_STAGE;      // 49152

// ---------------- device scratch (no runtime allocation allowed) ----------------
__device__ __half g_Xh[Bm * Dk];                      // normalized x, fp16
__device__ float g_rowsum[Bm];                        // sum_c exp(S*cos)
__device__ float g_lsum;                              // loss partial-sum accumulator
__device__ int   g_ldone;                             // loss block ticket counter
__device__ float g_cos_scratch[(size_t)Bm * (size_t)Cn]; // fallback cossim store

// ---------------- helpers ----------------
__device__ __forceinline__ uint32_t f2h2(float a, float b) {
    __half2 h = __floats2half2_rn(a, b);
    return *reinterpret_cast<uint32_t*>(&h);
}

__device__ __forceinline__ void mma16(float* d, const uint32_t* a, const uint32_t* b) {
    asm volatile(
        "mma.sync.aligned.m16n8k16.row.col.f32.f16.f16.f32 "
        "{%0,%1,%2,%3}, {%4,%5,%6,%7}, {%8,%9}, {%0,%1,%2,%3};\n"
        : "+f"(d[0]), "+f"(d[1]), "+f"(d[2]), "+f"(d[3])
        : "r"(a[0]), "r"(a[1]), "r"(a[2]), "r"(a[3]), "r"(b[0]), "r"(b[1]));
}
__device__ __forceinline__ void ldsm4(uint32_t* r, uint32_t addr) {
    asm volatile("ldmatrix.sync.aligned.m8n8.x4.shared.b16 {%0,%1,%2,%3}, [%4];"
                 : "=r"(r[0]), "=r"(r[1]), "=r"(r[2]), "=r"(r[3]) : "r"(addr));
}
__device__ __forceinline__ void ldsm4t(uint32_t* r, uint32_t addr) {
    asm volatile("ldmatrix.sync.aligned.m8n8.x4.trans.shared.b16 {%0,%1,%2,%3}, [%4];"
                 : "=r"(r[0]), "=r"(r[1]), "=r"(r[2]), "=r"(r[3]) : "r"(addr));
}
__device__ __forceinline__ void cp16(uint32_t smem_dst, const void* gsrc) {
    asm volatile("cp.async.cg.shared.global [%0], [%1], 16;"
                 :: "r"(smem_dst), "l"(gsrc) : "memory");
}
__device__ __forceinline__ void cp_commit() {
    asm volatile("cp.async.commit_group;" ::: "memory");
}
template <int N>
__device__ __forceinline__ void cp_wait() {
    asm volatile("cp.async.wait_group %0;" :: "n"(N) : "memory");
}

// swizzled byte offsets inside the smem tiles (16B cell granularity)
// A tile: 128 rows x 32 halfs (64B/row = 4 cells): cell ^= (row>>1)&3
__device__ __forceinline__ int a_byte(int r, int c) {
    return r * 64 + ((c ^ ((r >> 1) & 3)) << 4);
}
// B tile: 32 k-rows x 128 halfs (256B/row = 16 cells): cell ^= k&7
__device__ __forceinline__ int b_byte(int k, int c) {
    return k * 256 + ((c ^ (k & 7)) << 4);
}

// ---------------- kernel 1: L2-normalize rows of x -> fp16; zero accumulators ------
__global__ void normalize_x_kernel(const float* __restrict__ x) {
    const int b = blockIdx.x;           // 1024 blocks
    const int t = threadIdx.x;          // 128 threads
    float4 v = reinterpret_cast<const float4*>(x + (size_t)b * Dk)[t];
    float ss = v.x * v.x + v.y * v.y + v.z * v.z + v.w * v.w;
    #pragma unroll
    for (int o = 16; o > 0; o >>= 1) ss += __shfl_xor_sync(0xffffffffu, ss, o);
    __shared__ float ws[4];
    if ((t & 31) == 0) ws[t >> 5] = ss;
    __syncthreads();
    const float tot = ws[0] + ws[1] + ws[2] + ws[3];
    const float inv = 1.0f / fmaxf(sqrtf(tot), 1e-12f);
    uint2 st;
    st.x = f2h2(v.x * inv, v.y * inv);
    st.y = f2h2(v.z * inv, v.w * inv);
    reinterpret_cast<uint2*>(g_Xh + (size_t)b * Dk)[t] = st;
    if (t == 0) g_rowsum[b] = 0.0f;
    if (b == 0 && t == 0) { g_lsum = 0.0f; g_ldone = 0; }
}

// ---------------- kernel 2: fp16 GEMM, fp32-W direct consume + in-CTA winv ---------
// W is read as fp32 and converted at STS time; each CTA also accumulates per-column
// sum-of-squares from its own loads (it sees the full K range of its N-tile) and
// builds winv in smem. This removes the separate 307MB wprep pass entirely.
__global__ void __launch_bounds__(256, 2)
gemm_cos_kernel(const float* __restrict__ Wp, float* __restrict__ outp) {
    extern __shared__ __align__(128) uint8_t smem[];
    uint8_t* As = smem;                  // A_STAGES x 8KB (cp.async)
    uint8_t* Bs = smem + OFF_B;          // 2 x 8KB fp16 (double buffered)

    float* __restrict__ outc = outp ? outp : g_cos_scratch;

    const int tid  = threadIdx.x;
    const int lane = tid & 31;
    const int g    = lane >> 2;
    const int t    = lane & 3;
    const int warp = tid >> 5;
    const int wm   = warp & 1;    // 2 warps in M (64 rows each)
    const int wn   = warp >> 1;   // 4 warps in N (32 cols each)
    const int bN   = blockIdx.y * BNT;
    const int bM   = blockIdx.x * BMT;

    const uint32_t sA0 = (uint32_t)__cvta_generic_to_shared(As);
    const uint32_t sB0 = (uint32_t)__cvta_generic_to_shared(Bs);

    // ---- load coordinates ----
    // A (cp.async fp16): thread owns row tid>>1, cells ac0, ac0+1
    const int arow = tid >> 1;
    const int ac0  = (tid & 1) * 2;
    // B (fp32 LDG): thread owns k-row bk, 16 consecutive n starting at bn0
    const int bk   = tid >> 3;
    const int bc0  = (tid & 7) * 2;
    const int bn0  = bN + bc0 * 8;
    const bool bvalid = (bn0 + 16 <= Cn);   // Cn % 16 == 0 -> all-or-nothing

    const __half* Abase = g_Xh + (size_t)(bM + arow) * Dk + ac0 * 8;

    auto issue_A = [&](int s) {
        const int buf = s & (A_STAGES - 1);
        const int kc  = s * BKT;
        const uint32_t dA = sA0 + buf * A_STAGE;
        cp16(dA + a_byte(arow, ac0),     Abase + kc);
        cp16(dA + a_byte(arow, ac0 + 1), Abase + kc + 8);
    };

    float4 wreg[4];   // 16 fp32 W values (one k-row x 16 n) in flight
    auto ldg_B = [&](int s) {
        if (bvalid) {
            const float* Bp = Wp + (size_t)(s * BKT + bk) * Cn + bn0;
            wreg[0] = reinterpret_cast<const float4*>(Bp)[0];
            wreg[1] = reinterpret_cast<const float4*>(Bp)[1];
            wreg[2] = reinterpret_cast<const float4*>(Bp)[2];
            wreg[3] = reinterpret_cast<const float4*>(Bp)[3];
        } else {
            wreg[0] = wreg[1] = wreg[2] = wreg[3] = make_float4(0.f, 0.f, 0.f, 0.f);
        }
    };

    float sumsq[16];
    #pragma unroll
    for (int j = 0; j < 16; ++j) sumsq[j] = 0.0f;

    auto sts_B = [&](int buf) {
        // accumulate column sum-of-squares from this k-row's values
        #pragma unroll
        for (int q = 0; q < 4; ++q) {
            sumsq[4 * q + 0] = fmaf(wreg[q].x, wreg[q].x, sumsq[4 * q + 0]);
            sumsq[4 * q + 1] = fmaf(wreg[q].y, wreg[q].y, sumsq[4 * q + 1]);
            sumsq[4 * q + 2] = fmaf(wreg[q].z, wreg[q].z, sumsq[4 * q + 2]);
            sumsq[4 * q + 3] = fmaf(wreg[q].w, wreg[q].w, sumsq[4 * q + 3]);
        }
        uint8_t* Bb = Bs + buf * B_STAGE;
        uint4 c0, c1;
        c0.x = f2h2(wreg[0].x, wreg[0].y); c0.y = f2h2(wreg[0].z, wreg[0].w);
        c0.z = f2h2(wreg[1].x, wreg[1].y); c0.w = f2h2(wreg[1].z, wreg[1].w);
        c1.x = f2h2(wreg[2].x, wreg[2].y); c1.y = f2h2(wreg[2].z, wreg[2].w);
        c1.z = f2h2(wreg[3].x, wreg[3].y); c1.w = f2h2(wreg[3].z, wreg[3].w);
        *reinterpret_cast<uint4*>(Bb + b_byte(bk, bc0))     = c0;
        *reinterpret_cast<uint4*>(Bb + b_byte(bk, bc0 + 1)) = c1;
    };

    float acc[4][4][4];
    #pragma unroll
    for (int i = 0; i < 4; ++i)
        #pragma unroll
        for (int j = 0; j < 4; ++j)
            #pragma unroll
            for (int k = 0; k < 4; ++k) acc[i][j][k] = 0.0f;

    // per-lane ldmatrix address components
    const int rl = lane & 15;     // row within 16-row tile
    const int cp = lane >> 4;     // cell selector (second half of lanes)

    auto compute_chunk = [&](int buf) {
        const uint32_t sAb = sA0 + buf * A_STAGE;
        const uint32_t sBb = sB0 + (buf & 1) * B_STAGE;
        #pragma unroll
        for (int ks = 0; ks < 2; ++ks) {
            uint32_t af[4][4];
            uint32_t bf[4][2];
            #pragma unroll
            for (int mt = 0; mt < 4; ++mt)
                ldsm4(af[mt], sAb + a_byte(wm * 64 + mt * 16 + rl, ks * 2 + cp));
            #pragma unroll
            for (int j = 0; j < 2; ++j)
                ldsm4t(&bf[2 * j][0], sBb + b_byte(ks * 16 + rl, wn * 4 + 2 * j + cp));
            #pragma unroll
            for (int mt = 0; mt < 4; ++mt)
                #pragma unroll
                for (int nt = 0; nt < 4; ++nt)
                    mma16(acc[mt][nt], af[mt], bf[nt]);
        }
    };

    // ---- prologue ----
    ldg_B(0);
    issue_A(0); cp_commit();
    issue_A(1); cp_commit();
    issue_A(2); cp_commit();
    sts_B(0);          // stalls on ldg_B(0) completion (prologue only)
    ldg_B(1);

    // ---- mainloop ----
    #pragma unroll
    for (int it = 0; it < NCHUNK; ++it) {
        cp_wait<2>();
        __syncthreads();                      // A(it) + B(it) visible to all
        if (it + 3 < NCHUNK) issue_A(it + 3);
        cp_commit();
        if (it + 1 < NCHUNK) {
            sts_B((it + 1) & 1);              // consumes wreg (loaded last iter)
            if (it + 2 < NCHUNK) ldg_B(it + 2);
        }
        compute_chunk(it & 3);
    }

    // ---- build winv in smem from per-thread sumsq ----
    cp_wait<0>();
    __syncthreads();                          // mainloop smem reads done; reuse A region
    float* colss  = reinterpret_cast<float*>(smem);          // [128][33] padded
    float* winv_s = reinterpret_cast<float*>(smem + 17536);  // 128 floats
    #pragma unroll
    for (int j = 0; j < 16; ++j)
        colss[((tid & 7) * 16 + j) * 33 + (tid >> 3)] = sumsq[j];
    __syncthreads();
    if (tid < BNT) {
        float s = 0.0f;
        #pragma unroll 8
        for (int r = 0; r < 32; ++r) s += colss[tid * 33 + r];
        winv_s[tid] = 1.0f / fmaxf(sqrtf(s), 1e-12f);
    }
    __syncthreads();

    // -------- fused epilogue: scale by 1/||w_c||, clip, store, accumulate exp-sums ----
    float rsum[4][2];
    #pragma unroll
    for (int mt = 0; mt < 4; ++mt) { rsum[mt][0] = 0.0f; rsum[mt][1] = 0.0f; }

    #pragma unroll
    for (int mt = 0; mt < 4; ++mt) {
        const int gr0 = bM + wm * 64 + mt * 16 + g;
        #pragma unroll
        for (int nt = 0; nt < 4; ++nt) {
            const int nl = wn * 32 + nt * 8 + t * 2;
            const int gc = bN + nl;
            if (gc < Cn) {
                const float iw0 = winv_s[nl];
                const float iw1 = winv_s[nl + 1];
                float c0 = fminf(fmaxf(acc[mt][nt][0] * iw0, -1.0f), 1.0f);
                float c1 = fminf(fmaxf(acc[mt][nt][1] * iw1, -1.0f), 1.0f);
                float c2 = fminf(fmaxf(acc[mt][nt][2] * iw0, -1.0f), 1.0f);
                float c3 = fminf(fmaxf(acc[mt][nt][3] * iw1, -1.0f), 1.0f);
                *reinterpret_cast<float2*>(&outc[(size_t)gr0 * Cn + gc]) = make_float2(c0, c1);
                *reinterpret_cast<float2*>(&outc[(size_t)(gr0 + 8) * Cn + gc]) = make_float2(c2, c3);
                rsum[mt][0] += __expf(S_s * c0) + __expf(S_s * c1);
                rsum[mt][1] += __expf(S_s * c2) + __expf(S_s * c3);
            }
        }
    }
    #pragma unroll
    for (int mt = 0; mt < 4; ++mt) {
        #pragma unroll
        for (int h = 0; h < 2; ++h) {
            float v = rsum[mt][h];
            v += __shfl_xor_sync(0xffffffffu, v, 1);
            v += __shfl_xor_sync(0xffffffffu, v, 2);
            if (t == 0) {
                const int gr = bM + wm * 64 + mt * 16 + g + h * 8;
                atomicAdd(&g_rowsum[gr], v);
            }
        }
    }
}

// ---------------- kernel 3: parallel per-row loss (reads cossim) ----------------
__global__ void loss_kernel(const float* __restrict__ cosp_param,
                            const int* __restrict__ lbl32,
                            float* __restrict__ loss_out) {
    const float* cosp = cosp_param ? cosp_param : g_cos_scratch;
    const int b = blockIdx.x * 128 + threadIdx.x;   // grid 8 x 128 threads

    __shared__ int nz;
    if (threadIdx.x == 0) nz = 0;
    __syncthreads();
    if (lbl32[2 * b + 1] != 0) atomicOr(&nz, 1);
    __syncthreads();

    int label;
    if (nz == 0) label = (int)(reinterpret_cast<const long long*>(lbl32)[b]);
    else         label = lbl32[b];

    const float tgt  = cosp[(size_t)b * Cn + label];
    const float excl = g_rowsum[b] - __expf(S_s * tgt);
    const float num  = S_s * (tgt - M_m);
    const float L    = num - logf(expf(num) + excl);

    float v = L;
    #pragma unroll
    for (int o = 16; o > 0; o >>= 1) v += __shfl_xor_sync(0xffffffffu, v, o);
    __shared__ float red[4];
    if ((threadIdx.x & 31) == 0) red[threadIdx.x >> 5] = v;
    __syncthreads();
    if (threadIdx.x == 0) {
        const float s = red[0] + red[1] + red[2] + red[3];
        atomicAdd(&g_lsum, s);
        __threadfence();
        const int tkt = atomicAdd(&g_ldone, 1);
        if (tkt == (int)gridDim.x - 1) {
            const float total = atomicAdd(&g_lsum, 0.0f);
            loss_out[0] = -(total / (float)Bm);
        }
    }
}

// ---------------- launch ----------------
extern "C" void kernel_launch(void* const* d_in, const int* in_sizes, int n_in,
                              void* d_out, int out_size) {
    const float* x   = (const float*)d_in[0];
    const float* W   = (const float*)d_in[1];
    const int*   lbl = (const int*)d_in[2];
    float* out = (float*)d_out;

    const long long BC = (long long)Bm * (long long)Cn;   // 102,400,000
    const bool cos_in_out = ((long long)out_size >= BC);

    static bool attr_set = false;
    if (!attr_set) {
        cudaFuncSetAttribute(gemm_cos_kernel,
                             cudaFuncAttributeMaxDynamicSharedMemorySize, SMEM_BYTES);
        attr_set = true;
    }

    normalize_x_kernel<<<Bm, 128>>>(x);

    // grid: x = M-blocks (8, fast-moving), y = N-blocks (782) -> W tiles L2-shared
    dim3 gg(Bm / BMT, (Cn + BNT - 1) / BNT);   // (8, 782)
    gemm_cos_kernel<<<gg, 256, SMEM_BYTES>>>(W, cos_in_out ? out : nullptr);

    if (cos_in_out && (long long)out_size >= BC + 1) {
        loss_kernel<<<8, 128>>>(out, lbl, out + BC);
    } else if (!cos_in_out && out_size >= 1) {
        loss_kernel<<<8, 128>>>(nullptr, lbl, out);
    }
}